// round 6
// baseline (speedup 1.0000x reference)
#include <cuda_runtime.h>
#include <cuda_fp16.h>

#define Bc 2
#define Hc 12
#define Sc 2048
#define Dc 64
#define TQ 64
#define TK 64
#define NTH 256
#define STRD 72           // smem row stride in halves (64 + 8 pad)
#define SCALE 0.125f      // 1/sqrt(64)

// fp16 scratch: log(freq) where mask!=0 else -60000 (fp32 exp -> exactly 0)
__device__ __align__(16) __half g_fm[(size_t)Bc * Sc * Sc];

__global__ void prep_fm_kernel(const float* __restrict__ freq,
                               const int*  __restrict__ mask) {
    size_t base = ((size_t)blockIdx.x * blockDim.x + threadIdx.x) * 4;
    float4 f = *(const float4*)(freq + base);
    int4   m = *(const int4*)(mask + base);
    __half2 lo = __floats2half2_rn(m.x ? __logf(f.x) : -60000.0f,
                                   m.y ? __logf(f.y) : -60000.0f);
    __half2 hi = __floats2half2_rn(m.z ? __logf(f.z) : -60000.0f,
                                   m.w ? __logf(f.w) : -60000.0f);
    uint2 u;
    u.x = *(unsigned*)&lo;
    u.y = *(unsigned*)&hi;
    *(uint2*)(g_fm + base) = u;
}

__device__ __forceinline__ void mma_f16(float* c, const unsigned* a, const unsigned* b) {
    asm volatile(
        "mma.sync.aligned.m16n8k16.row.col.f32.f16.f16.f32 "
        "{%0,%1,%2,%3}, {%4,%5,%6,%7}, {%8,%9}, {%0,%1,%2,%3};\n"
        : "+f"(c[0]), "+f"(c[1]), "+f"(c[2]), "+f"(c[3])
        : "r"(a[0]), "r"(a[1]), "r"(a[2]), "r"(a[3]), "r"(b[0]), "r"(b[1]));
}

__global__ void __launch_bounds__(NTH)
attn_kernel(const float* __restrict__ Q, const float* __restrict__ K,
            const float* __restrict__ V, float* __restrict__ Out,
            float* __restrict__ Pout, int writep) {
    __shared__ __align__(16) __half Qs[TQ * STRD];   // [q][d]
    __shared__ __align__(16) __half Ks[TK * STRD];   // [key][d]
    __shared__ __align__(16) __half Vt[Dc * STRD];   // [d][key]
    __shared__ __align__(16) __half Ps[TQ * STRD];   // [q][key] normalized p
    __shared__ __align__(16) __half FMs[TQ * STRD];  // [q][key] log-freq/mask
    __shared__ float Zp[2][TQ];
    __shared__ float Zf[TQ];

    const int tid = threadIdx.x;
    const int w = tid >> 5, lane = tid & 31;
    const int g = lane >> 2, tg = lane & 3;
    const int wm = w >> 1, wn = w & 1;            // 4 m-warps x 2 n-warps
    const int h = blockIdx.x, qt = blockIdx.y, b = blockIdx.z;
    const int q0 = qt * TQ;
    const int arow = wm * 16 + g;                 // thread's low row (0..63)

    const size_t bh = (size_t)b * Hc + h;
    const float* Qg = Q + (bh * Sc + q0) * Dc;
    const float* Kg = K + bh * Sc * Dc;
    const float* Vg = V + bh * Sc * Dc;
    const __half* FMg = g_fm + (size_t)b * Sc * Sc + (size_t)q0 * Sc;
    float* Og = Out + (bh * Sc + q0) * Dc;
    float* Pg = Pout + (bh * Sc + q0) * Sc;

    // stage Q tile (lives for whole CTA)
    #pragma unroll
    for (int i = tid; i < TQ * 16; i += NTH) {
        int r = i >> 4, c = (i & 15) * 4;
        float4 v = *(const float4*)(Qg + (size_t)r * Dc + c);
        __half2 p0 = __floats2half2_rn(v.x, v.y), p1 = __floats2half2_rn(v.z, v.w);
        uint2 u; u.x = *(unsigned*)&p0; u.y = *(unsigned*)&p1;
        *(uint2*)(Qs + r * STRD + c) = u;
    }

    float oacc[4][4];
    #pragma unroll
    for (int nt = 0; nt < 4; ++nt)
        oacc[nt][0] = oacc[nt][1] = oacc[nt][2] = oacc[nt][3] = 0.0f;
    float zlo = 0.0f, zhi = 0.0f;

    for (int pass = 0; pass < 2; ++pass) {
        for (int kt = 0; kt < Sc / TK; ++kt) {
            __syncthreads();
            #pragma unroll
            for (int i = tid; i < TK * 16; i += NTH) {   // K tile
                int r = i >> 4, c = (i & 15) * 4;
                float4 v = *(const float4*)(Kg + (size_t)(kt * TK + r) * Dc + c);
                __half2 p0 = __floats2half2_rn(v.x, v.y), p1 = __floats2half2_rn(v.z, v.w);
                uint2 u; u.x = *(unsigned*)&p0; u.y = *(unsigned*)&p1;
                *(uint2*)(Ks + r * STRD + c) = u;
            }
            #pragma unroll
            for (int i = tid; i < TQ * 8; i += NTH) {    // FM tile
                int r = i >> 3, c = (i & 7) * 8;
                *(uint4*)(FMs + r * STRD + c) =
                    *(const uint4*)(FMg + (size_t)r * Sc + kt * TK + c);
            }
            if (pass) {
                #pragma unroll
                for (int i = tid; i < TK * 16; i += NTH) {  // V tile, transposed
                    int r = i >> 4, c = (i & 15) * 4;
                    float4 v = *(const float4*)(Vg + (size_t)(kt * TK + r) * Dc + c);
                    Vt[(c + 0) * STRD + r] = __float2half(v.x);
                    Vt[(c + 1) * STRD + r] = __float2half(v.y);
                    Vt[(c + 2) * STRD + r] = __float2half(v.z);
                    Vt[(c + 3) * STRD + r] = __float2half(v.w);
                }
            }
            __syncthreads();

            // QK^T scores: each warp 16x32
            float sacc[4][4];
            #pragma unroll
            for (int nt = 0; nt < 4; ++nt)
                sacc[nt][0] = sacc[nt][1] = sacc[nt][2] = sacc[nt][3] = 0.0f;
            #pragma unroll
            for (int ks = 0; ks < 4; ++ks) {
                unsigned a[4];
                int ac = ks * 16 + 2 * tg;
                a[0] = *(const unsigned*)(Qs + arow * STRD + ac);
                a[1] = *(const unsigned*)(Qs + (arow + 8) * STRD + ac);
                a[2] = *(const unsigned*)(Qs + arow * STRD + ac + 8);
                a[3] = *(const unsigned*)(Qs + (arow + 8) * STRD + ac + 8);
                #pragma unroll
                for (int nt = 0; nt < 4; ++nt) {
                    int kb = wn * 32 + nt * 8;
                    unsigned bb[2];
                    bb[0] = *(const unsigned*)(Ks + (kb + g) * STRD + ac);
                    bb[1] = *(const unsigned*)(Ks + (kb + g) * STRD + ac + 8);
                    mma_f16(sacc[nt], a, bb);
                }
            }

            if (!pass) {
                #pragma unroll
                for (int nt = 0; nt < 4; ++nt) {
                    int col = wn * 32 + nt * 8 + 2 * tg;
                    float2 flo = __half22float2(*(const __half2*)(FMs + arow * STRD + col));
                    float2 fhi = __half22float2(*(const __half2*)(FMs + (arow + 8) * STRD + col));
                    zlo += __expf(fmaf(sacc[nt][0], SCALE, flo.x))
                         + __expf(fmaf(sacc[nt][1], SCALE, flo.y));
                    zhi += __expf(fmaf(sacc[nt][2], SCALE, fhi.x))
                         + __expf(fmaf(sacc[nt][3], SCALE, fhi.y));
                }
            } else {
                const float izlo = Zf[arow], izhi = Zf[arow + 8];
                #pragma unroll
                for (int nt = 0; nt < 4; ++nt) {
                    int col = wn * 32 + nt * 8 + 2 * tg;
                    float2 flo = __half22float2(*(const __half2*)(FMs + arow * STRD + col));
                    float2 fhi = __half22float2(*(const __half2*)(FMs + (arow + 8) * STRD + col));
                    float p0 = __expf(fmaf(sacc[nt][0], SCALE, flo.x)) * izlo;
                    float p1 = __expf(fmaf(sacc[nt][1], SCALE, flo.y)) * izlo;
                    float p2 = __expf(fmaf(sacc[nt][2], SCALE, fhi.x)) * izhi;
                    float p3 = __expf(fmaf(sacc[nt][3], SCALE, fhi.y)) * izhi;
                    if (writep) {
                        *(float2*)(Pg + (size_t)arow * Sc + kt * TK + col)       = make_float2(p0, p1);
                        *(float2*)(Pg + (size_t)(arow + 8) * Sc + kt * TK + col) = make_float2(p2, p3);
                    }
                    *(__half2*)(Ps + arow * STRD + col)       = __floats2half2_rn(p0, p1);
                    *(__half2*)(Ps + (arow + 8) * STRD + col) = __floats2half2_rn(p2, p3);
                }
                __syncthreads();

                // PV: oacc[16x32 d-cols] += P[16x64] * V[64x32]
                #pragma unroll
                for (int ks = 0; ks < 4; ++ks) {
                    unsigned a[4];
                    int ac = ks * 16 + 2 * tg;
                    a[0] = *(const unsigned*)(Ps + arow * STRD + ac);
                    a[1] = *(const unsigned*)(Ps + (arow + 8) * STRD + ac);
                    a[2] = *(const unsigned*)(Ps + arow * STRD + ac + 8);
                    a[3] = *(const unsigned*)(Ps + (arow + 8) * STRD + ac + 8);
                    #pragma unroll
                    for (int nt = 0; nt < 4; ++nt) {
                        int db = wn * 32 + nt * 8;
                        unsigned bb[2];
                        bb[0] = *(const unsigned*)(Vt + (db + g) * STRD + ac);
                        bb[1] = *(const unsigned*)(Vt + (db + g) * STRD + ac + 8);
                        mma_f16(oacc[nt], a, bb);
                    }
                }
            }
        } // kt

        if (!pass) {
            // deterministic Z reduction: shfl over tg, smem over the 2 n-warps
            zlo += __shfl_xor_sync(0xffffffffu, zlo, 1);
            zlo += __shfl_xor_sync(0xffffffffu, zlo, 2);
            zhi += __shfl_xor_sync(0xffffffffu, zhi, 1);
            zhi += __shfl_xor_sync(0xffffffffu, zhi, 2);
            if (tg == 0) {
                Zp[wn][arow]     = zlo;
                Zp[wn][arow + 8] = zhi;
            }
            __syncthreads();
            if (tid < TQ) Zf[tid] = 1.0f / (Zp[0][tid] + Zp[1][tid]);
        }
    } // pass

    // write out tile
    #pragma unroll
    for (int nt = 0; nt < 4; ++nt) {
        int col = wn * 32 + nt * 8 + 2 * tg;
        *(float2*)(Og + (size_t)arow * Dc + col)       = make_float2(oacc[nt][0], oacc[nt][1]);
        *(float2*)(Og + (size_t)(arow + 8) * Dc + col) = make_float2(oacc[nt][2], oacc[nt][3]);
    }
}

extern "C" void kernel_launch(void* const* d_in, const int* in_sizes, int n_in,
                              void* d_out, int out_size) {
    const float* Q    = (const float*)d_in[0];
    const float* K    = (const float*)d_in[1];
    const float* V    = (const float*)d_in[2];
    const float* freq = (const float*)d_in[3];
    const int*   mask = (const int*)d_in[4];

    const size_t out_elems = (size_t)Bc * Hc * Sc * Dc;   // 3,145,728
    float* Out  = (float*)d_out;
    float* Pout = (float*)d_out + out_elems;              // p_attn follows out
    int writep  = (out_size > (int)out_elems) ? 1 : 0;

    // prep: B*S*S elems, 4 per thread
    {
        int total = Bc * Sc * Sc;
        int blocks = total / (256 * 4);
        prep_fm_kernel<<<blocks, 256>>>(freq, mask);
    }
    // attention: h fastest for freq/mask L2 reuse across heads
    {
        dim3 grid(Hc, Sc / TQ, Bc);
        attn_kernel<<<grid, NTH>>>(Q, K, V, Out, Pout, writep);
    }
}

// round 7
// speedup vs baseline: 1.2742x; 1.2742x over previous
#include <cuda_runtime.h>
#include <cuda_fp16.h>

#define Bc 2
#define Hc 12
#define Sc 2048
#define Dc 64
#define TQ 64
#define TK 64
#define NTH 128
#define STRD 72           // smem row stride in halves (64 + 8 pad, 144B)
#define SCALE 0.125f      // 1/sqrt(64)

// fp16 scratch: log(freq) where mask!=0 else -60000 (fp32 exp -> exactly 0)
__device__ __align__(16) __half g_fm[(size_t)Bc * Sc * Sc];

__global__ void prep_fm_kernel(const float* __restrict__ freq,
                               const int*  __restrict__ mask) {
    size_t base = ((size_t)blockIdx.x * blockDim.x + threadIdx.x) * 4;
    float4 f = *(const float4*)(freq + base);
    int4   m = *(const int4*)(mask + base);
    __half2 lo = __floats2half2_rn(m.x ? __logf(f.x) : -60000.0f,
                                   m.y ? __logf(f.y) : -60000.0f);
    __half2 hi = __floats2half2_rn(m.z ? __logf(f.z) : -60000.0f,
                                   m.w ? __logf(f.w) : -60000.0f);
    uint2 u;
    u.x = *(unsigned*)&lo;
    u.y = *(unsigned*)&hi;
    *(uint2*)(g_fm + base) = u;
}

__device__ __forceinline__ void mma_f16(float* c, const unsigned* a, const unsigned* b) {
    asm volatile(
        "mma.sync.aligned.m16n8k16.row.col.f32.f16.f16.f32 "
        "{%0,%1,%2,%3}, {%4,%5,%6,%7}, {%8,%9}, {%0,%1,%2,%3};\n"
        : "+f"(c[0]), "+f"(c[1]), "+f"(c[2]), "+f"(c[3])
        : "r"(a[0]), "r"(a[1]), "r"(a[2]), "r"(a[3]), "r"(b[0]), "r"(b[1]));
}

__device__ __forceinline__ void ldsm4(unsigned& r0, unsigned& r1, unsigned& r2,
                                      unsigned& r3, unsigned addr) {
    asm volatile("ldmatrix.sync.aligned.m8n8.x4.shared.b16 {%0,%1,%2,%3}, [%4];"
                 : "=r"(r0), "=r"(r1), "=r"(r2), "=r"(r3) : "r"(addr));
}

__device__ __forceinline__ void ldsm4t(unsigned& r0, unsigned& r1, unsigned& r2,
                                       unsigned& r3, unsigned addr) {
    asm volatile("ldmatrix.sync.aligned.m8n8.x4.trans.shared.b16 {%0,%1,%2,%3}, [%4];"
                 : "=r"(r0), "=r"(r1), "=r"(r2), "=r"(r3) : "r"(addr));
}

// QK^T: warp computes 16x64 scores over k=64 via ldmatrix + mma
__device__ __forceinline__ void qk_mma(float sacc[8][4], unsigned addrA, unsigned addrB) {
    #pragma unroll
    for (int ks = 0; ks < 4; ++ks) {
        unsigned a[4];
        ldsm4(a[0], a[1], a[2], a[3], addrA + ks * 32);        // +16 halves per ks
        #pragma unroll
        for (int ntp = 0; ntp < 4; ++ntp) {
            unsigned b0, b1, b2, b3;
            ldsm4(b0, b1, b2, b3, addrB + (ntp * 16 * STRD + ks * 16) * 2);
            unsigned blo[2] = {b0, b1}, bhi[2] = {b2, b3};
            mma_f16(sacc[2 * ntp],     a, blo);
            mma_f16(sacc[2 * ntp + 1], a, bhi);
        }
    }
}

__global__ void __launch_bounds__(NTH)
attn_kernel(const float* __restrict__ Q, const float* __restrict__ K,
            const float* __restrict__ V, float* __restrict__ Out,
            float* __restrict__ Pout, int writep) {
    __shared__ __align__(16) __half Qs[TQ * STRD];   // [q][d]
    __shared__ __align__(16) __half Ks[TK * STRD];   // [key][d]
    __shared__ __align__(16) __half Vs[TK * STRD];   // [key][d] (NOT transposed)

    const int tid = threadIdx.x;
    const int w = tid >> 5, lane = tid & 31;
    const int g = lane >> 2, tg = lane & 3;
    const int wq = w * 16;                       // warp's row base within tile
    const int h = blockIdx.x, qt = blockIdx.y, b = blockIdx.z;
    const int q0 = qt * TQ;
    const int arow = wq + g;

    const size_t bh = (size_t)b * Hc + h;
    const float* Qg = Q + (bh * Sc + q0) * Dc;
    const float* Kg = K + bh * Sc * Dc;
    const float* Vg = V + bh * Sc * Dc;
    const __half* FMg = g_fm + (size_t)b * Sc * Sc + (size_t)q0 * Sc;
    float* Og = Out + (bh * Sc + q0) * Dc;
    float* Pg = Pout + (bh * Sc + q0) * Sc;

    // FM row pointers (half2 granularity)
    const __half2* fm0 = (const __half2*)(FMg + (size_t)arow * Sc);
    const __half2* fm1 = (const __half2*)(FMg + (size_t)(arow + 8) * Sc);

    // ldmatrix per-lane base addresses
    const unsigned qs_u = (unsigned)__cvta_generic_to_shared(Qs);
    const unsigned ks_u = (unsigned)__cvta_generic_to_shared(Ks);
    const unsigned vs_u = (unsigned)__cvta_generic_to_shared(Vs);
    // A (Q): m0=rows0-7 klo, m1=rows8-15 klo, m2=rows0-7 khi, m3=rows8-15 khi
    const unsigned addrA = qs_u + (((wq + (lane & 15)) * STRD + (lane >> 4) * 8) << 1);
    // B (K): m0=(n0-7,klo) m1=(n0-7,khi) m2=(n8-15,klo) m3=(n8-15,khi)
    const int brow = ((lane >> 4) & 1) * 8 + (lane & 7);
    const int bcol = ((lane >> 3) & 1) * 8;
    const unsigned addrB = ks_u + ((brow * STRD + bcol) << 1);
    // V (trans): m0=(klo,n0-7) m1=(khi,n0-7) m2=(klo,n8-15) m3=(khi,n8-15)
    const int vrow = ((lane >> 3) & 1) * 8 + (lane & 7);
    const int vcol = ((lane >> 4) & 1) * 8;
    const unsigned addrV = vs_u + ((vrow * STRD + vcol) << 1);

    // stage Q tile (lives for whole CTA)
    #pragma unroll
    for (int i = tid; i < TQ * 16; i += NTH) {
        int r = i >> 4, c = (i & 15) * 4;
        float4 v = *(const float4*)(Qg + (size_t)r * Dc + c);
        __half2 p0 = __floats2half2_rn(v.x, v.y), p1 = __floats2half2_rn(v.z, v.w);
        uint2 u; u.x = *(unsigned*)&p0; u.y = *(unsigned*)&p1;
        *(uint2*)(Qs + r * STRD + c) = u;
    }

    // ---------------- pass 1: row sums Z ----------------
    float zlo = 0.0f, zhi = 0.0f;
    for (int kt = 0; kt < Sc / TK; ++kt) {
        __syncthreads();
        #pragma unroll
        for (int i = tid; i < TK * 16; i += NTH) {   // K tile
            int r = i >> 4, c = (i & 15) * 4;
            float4 v = *(const float4*)(Kg + (size_t)(kt * TK + r) * Dc + c);
            __half2 p0 = __floats2half2_rn(v.x, v.y), p1 = __floats2half2_rn(v.z, v.w);
            uint2 u; u.x = *(unsigned*)&p0; u.y = *(unsigned*)&p1;
            *(uint2*)(Ks + r * STRD + c) = u;
        }
        __syncthreads();

        float sacc[8][4];
        #pragma unroll
        for (int nt = 0; nt < 8; ++nt)
            sacc[nt][0] = sacc[nt][1] = sacc[nt][2] = sacc[nt][3] = 0.0f;
        qk_mma(sacc, addrA, addrB);

        int cb = kt * 32 + tg;                    // half2 col index base
        #pragma unroll
        for (int nt = 0; nt < 8; ++nt) {
            float2 flo = __half22float2(fm0[cb + nt * 4]);
            float2 fhi = __half22float2(fm1[cb + nt * 4]);
            zlo += __expf(fmaf(sacc[nt][0], SCALE, flo.x))
                 + __expf(fmaf(sacc[nt][1], SCALE, flo.y));
            zhi += __expf(fmaf(sacc[nt][2], SCALE, fhi.x))
                 + __expf(fmaf(sacc[nt][3], SCALE, fhi.y));
        }
    }
    // full row owned by this warp: reduce over the 4 tg lanes only
    zlo += __shfl_xor_sync(0xffffffffu, zlo, 1);
    zlo += __shfl_xor_sync(0xffffffffu, zlo, 2);
    zhi += __shfl_xor_sync(0xffffffffu, zhi, 1);
    zhi += __shfl_xor_sync(0xffffffffu, zhi, 2);
    const float izlo = 1.0f / zlo;
    const float izhi = 1.0f / zhi;

    // ---------------- pass 2: emit P, accumulate O ----------------
    float oacc[8][4];
    #pragma unroll
    for (int nt = 0; nt < 8; ++nt)
        oacc[nt][0] = oacc[nt][1] = oacc[nt][2] = oacc[nt][3] = 0.0f;

    float2* Pg0 = (float2*)(Pg + (size_t)arow * Sc);
    float2* Pg1 = (float2*)(Pg + (size_t)(arow + 8) * Sc);

    for (int kt = 0; kt < Sc / TK; ++kt) {
        __syncthreads();
        #pragma unroll
        for (int i = tid; i < TK * 16; i += NTH) {   // K tile
            int r = i >> 4, c = (i & 15) * 4;
            float4 v = *(const float4*)(Kg + (size_t)(kt * TK + r) * Dc + c);
            __half2 p0 = __floats2half2_rn(v.x, v.y), p1 = __floats2half2_rn(v.z, v.w);
            uint2 u; u.x = *(unsigned*)&p0; u.y = *(unsigned*)&p1;
            *(uint2*)(Ks + r * STRD + c) = u;
        }
        #pragma unroll
        for (int i = tid; i < TK * 16; i += NTH) {   // V tile (raw layout)
            int r = i >> 4, c = (i & 15) * 4;
            float4 v = *(const float4*)(Vg + (size_t)(kt * TK + r) * Dc + c);
            __half2 p0 = __floats2half2_rn(v.x, v.y), p1 = __floats2half2_rn(v.z, v.w);
            uint2 u; u.x = *(unsigned*)&p0; u.y = *(unsigned*)&p1;
            *(uint2*)(Vs + r * STRD + c) = u;
        }
        __syncthreads();

        float sacc[8][4];
        #pragma unroll
        for (int nt = 0; nt < 8; ++nt)
            sacc[nt][0] = sacc[nt][1] = sacc[nt][2] = sacc[nt][3] = 0.0f;
        qk_mma(sacc, addrA, addrB);

        // normalized P: write to gmem (streaming) + pack fp16 A-fragments
        unsigned ph_lo[8], ph_hi[8];
        int cb = kt * 32 + tg;
        #pragma unroll
        for (int nt = 0; nt < 8; ++nt) {
            float2 flo = __half22float2(fm0[cb + nt * 4]);
            float2 fhi = __half22float2(fm1[cb + nt * 4]);
            float p0 = __expf(fmaf(sacc[nt][0], SCALE, flo.x)) * izlo;
            float p1 = __expf(fmaf(sacc[nt][1], SCALE, flo.y)) * izlo;
            float p2 = __expf(fmaf(sacc[nt][2], SCALE, fhi.x)) * izhi;
            float p3 = __expf(fmaf(sacc[nt][3], SCALE, fhi.y)) * izhi;
            if (writep) {
                __stwt(Pg0 + cb + nt * 4, make_float2(p0, p1));
                __stwt(Pg1 + cb + nt * 4, make_float2(p2, p3));
            }
            __half2 hlo = __floats2half2_rn(p0, p1);
            __half2 hhi = __floats2half2_rn(p2, p3);
            ph_lo[nt] = *(unsigned*)&hlo;
            ph_hi[nt] = *(unsigned*)&hhi;
        }

        // PV: oacc[16 x 64d] += P[16 x 64k] * V[64k x 64d]
        // A-fragments come straight from registers (S-accum layout == A layout)
        #pragma unroll
        for (int ks2 = 0; ks2 < 4; ++ks2) {
            unsigned a[4];
            a[0] = ph_lo[2 * ks2];
            a[1] = ph_hi[2 * ks2];
            a[2] = ph_lo[2 * ks2 + 1];
            a[3] = ph_hi[2 * ks2 + 1];
            #pragma unroll
            for (int ntp = 0; ntp < 4; ++ntp) {
                unsigned v0, v1, v2, v3;
                ldsm4t(v0, v1, v2, v3, addrV + (ks2 * 16 * STRD + ntp * 16) * 2);
                unsigned blo[2] = {v0, v1}, bhi[2] = {v2, v3};
                mma_f16(oacc[2 * ntp],     a, blo);
                mma_f16(oacc[2 * ntp + 1], a, bhi);
            }
        }
    }

    // write O tile: rows arow, arow+8; cols nt*8 + 2tg
    #pragma unroll
    for (int nt = 0; nt < 8; ++nt) {
        int col = nt * 8 + 2 * tg;
        *(float2*)(Og + (size_t)arow * Dc + col)       = make_float2(oacc[nt][0], oacc[nt][1]);
        *(float2*)(Og + (size_t)(arow + 8) * Dc + col) = make_float2(oacc[nt][2], oacc[nt][3]);
    }
}

extern "C" void kernel_launch(void* const* d_in, const int* in_sizes, int n_in,
                              void* d_out, int out_size) {
    const float* Q    = (const float*)d_in[0];
    const float* K    = (const float*)d_in[1];
    const float* V    = (const float*)d_in[2];
    const float* freq = (const float*)d_in[3];
    const int*   mask = (const int*)d_in[4];

    const size_t out_elems = (size_t)Bc * Hc * Sc * Dc;   // 3,145,728
    float* Out  = (float*)d_out;
    float* Pout = (float*)d_out + out_elems;              // p_attn follows out
    int writep  = (out_size > (int)out_elems) ? 1 : 0;

    {
        int total = Bc * Sc * Sc;
        int blocks = total / (256 * 4);
        prep_fm_kernel<<<blocks, 256>>>(freq, mask);
    }
    {
        dim3 grid(Hc, Sc / TQ, Bc);
        attn_kernel<<<grid, NTH>>>(Q, K, V, Out, Pout, writep);
    }
}

// round 8
// speedup vs baseline: 1.3649x; 1.0711x over previous
#include <cuda_runtime.h>
#include <cuda_fp16.h>

#define Bc 2
#define Hc 12
#define Sc 2048
#define Dc 64
#define TQ 128
#define TK 64
#define NTH 128
#define STRD 72           // smem row stride in halves (64 + 8 pad, 144B)
#define SCALE 0.125f      // 1/sqrt(64)

// scratch: fp16 log(freq)/-60000, fp16 K, fp16 V
__device__ __align__(16) __half g_fm[(size_t)Bc * Sc * Sc];
__device__ __align__(16) __half g_kh[(size_t)Bc * Hc * Sc * Dc];
__device__ __align__(16) __half g_vh[(size_t)Bc * Hc * Sc * Dc];

__global__ void prep_fm_kernel(const float* __restrict__ freq,
                               const int*  __restrict__ mask) {
    size_t base = ((size_t)blockIdx.x * blockDim.x + threadIdx.x) * 4;
    float4 f = *(const float4*)(freq + base);
    int4   m = *(const int4*)(mask + base);
    __half2 lo = __floats2half2_rn(m.x ? __logf(f.x) : -60000.0f,
                                   m.y ? __logf(f.y) : -60000.0f);
    __half2 hi = __floats2half2_rn(m.z ? __logf(f.z) : -60000.0f,
                                   m.w ? __logf(f.w) : -60000.0f);
    uint2 u;
    u.x = *(unsigned*)&lo;
    u.y = *(unsigned*)&hi;
    *(uint2*)(g_fm + base) = u;
}

__global__ void prep_kv_kernel(const float* __restrict__ K,
                               const float* __restrict__ V) {
    size_t base = ((size_t)blockIdx.x * blockDim.x + threadIdx.x) * 8;
    float4 a = *(const float4*)(K + base);
    float4 b = *(const float4*)(K + base + 4);
    __half2 h0 = __floats2half2_rn(a.x, a.y), h1 = __floats2half2_rn(a.z, a.w);
    __half2 h2 = __floats2half2_rn(b.x, b.y), h3 = __floats2half2_rn(b.z, b.w);
    uint4 u;
    u.x = *(unsigned*)&h0; u.y = *(unsigned*)&h1;
    u.z = *(unsigned*)&h2; u.w = *(unsigned*)&h3;
    *(uint4*)(g_kh + base) = u;
    a = *(const float4*)(V + base);
    b = *(const float4*)(V + base + 4);
    h0 = __floats2half2_rn(a.x, a.y); h1 = __floats2half2_rn(a.z, a.w);
    h2 = __floats2half2_rn(b.x, b.y); h3 = __floats2half2_rn(b.z, b.w);
    u.x = *(unsigned*)&h0; u.y = *(unsigned*)&h1;
    u.z = *(unsigned*)&h2; u.w = *(unsigned*)&h3;
    *(uint4*)(g_vh + base) = u;
}

__device__ __forceinline__ void mma_f16(float* c, const unsigned* a, const unsigned* b) {
    asm volatile(
        "mma.sync.aligned.m16n8k16.row.col.f32.f16.f16.f32 "
        "{%0,%1,%2,%3}, {%4,%5,%6,%7}, {%8,%9}, {%0,%1,%2,%3};\n"
        : "+f"(c[0]), "+f"(c[1]), "+f"(c[2]), "+f"(c[3])
        : "r"(a[0]), "r"(a[1]), "r"(a[2]), "r"(a[3]), "r"(b[0]), "r"(b[1]));
}

__device__ __forceinline__ void ldsm4(unsigned& r0, unsigned& r1, unsigned& r2,
                                      unsigned& r3, unsigned addr) {
    asm volatile("ldmatrix.sync.aligned.m8n8.x4.shared.b16 {%0,%1,%2,%3}, [%4];"
                 : "=r"(r0), "=r"(r1), "=r"(r2), "=r"(r3) : "r"(addr));
}

__device__ __forceinline__ void ldsm4t(unsigned& r0, unsigned& r1, unsigned& r2,
                                       unsigned& r3, unsigned addr) {
    asm volatile("ldmatrix.sync.aligned.m8n8.x4.trans.shared.b16 {%0,%1,%2,%3}, [%4];"
                 : "=r"(r0), "=r"(r1), "=r"(r2), "=r"(r3) : "r"(addr));
}

__global__ void __launch_bounds__(NTH)
attn_kernel(const float* __restrict__ Q, float* __restrict__ Out,
            float* __restrict__ Pout, int writep) {
    // static smem: Ks | FMs | Vs ; Q staging overlays Ks+FMs (transient)
    __shared__ __align__(16) __half smem_buf[(TK + TQ + TK) * STRD];
    __half* Ks  = smem_buf;                       // 64  x STRD
    __half* FMs = smem_buf + TK * STRD;           // 128 x STRD
    __half* Vs  = smem_buf + (TK + TQ) * STRD;    // 64  x STRD
    __half* Qst = smem_buf;                       // 128 x STRD transient

    const int tid = threadIdx.x;
    const int w = tid >> 5, lane = tid & 31;
    const int g = lane >> 2, tg = lane & 3;
    const int wq = w * 32;                        // warp's 32-row base
    const int h = blockIdx.x, qt = blockIdx.y, b = blockIdx.z;
    const int q0 = qt * TQ;

    const size_t bh = (size_t)b * Hc + h;
    const float*  Qg = Q + (bh * Sc + q0) * Dc;
    const __half* Kh = g_kh + bh * Sc * Dc;
    const __half* Vh = g_vh + bh * Sc * Dc;
    const __half* FMg = g_fm + (size_t)b * Sc * Sc + (size_t)q0 * Sc;
    float* Og = Out + (bh * Sc + q0) * Dc;
    float* Pg = Pout + (bh * Sc + q0) * Sc;

    const unsigned smem_u = (unsigned)__cvta_generic_to_shared(smem_buf);
    const unsigned ks_u = smem_u;
    const unsigned vs_u = smem_u + (TK + TQ) * STRD * 2;
    // B (K): m0=(n0-7,klo) m1=(n0-7,khi) m2=(n8-15,klo) m3=(n8-15,khi)
    const int brow = ((lane >> 4) & 1) * 8 + (lane & 7);
    const int bcol = ((lane >> 3) & 1) * 8;
    const unsigned addrB = ks_u + ((brow * STRD + bcol) << 1);
    // V (trans): m0=(klo,n0-7) m1=(khi,n0-7) m2=(klo,n8-15) m3=(khi,n8-15)
    const int vrow = ((lane >> 3) & 1) * 8 + (lane & 7);
    const int vcol = ((lane >> 4) & 1) * 8;
    const unsigned addrV = vs_u + ((vrow * STRD + vcol) << 1);

    // ---- stage Q tile fp32->fp16, then load A-fragments into registers ----
    #pragma unroll
    for (int i = tid; i < TQ * 16; i += NTH) {
        int r = i >> 4, c = (i & 15) * 4;
        float4 v = *(const float4*)(Qg + (size_t)r * Dc + c);
        __half2 p0 = __floats2half2_rn(v.x, v.y), p1 = __floats2half2_rn(v.z, v.w);
        uint2 u; u.x = *(unsigned*)&p0; u.y = *(unsigned*)&p1;
        *(uint2*)(Qst + r * STRD + c) = u;
    }
    __syncthreads();
    unsigned qa[2][4][4];
    #pragma unroll
    for (int mb = 0; mb < 2; ++mb) {
        unsigned addrA = smem_u +
            (((wq + 16 * mb + (lane & 15)) * STRD + (lane >> 4) * 8) << 1);
        #pragma unroll
        for (int ks = 0; ks < 4; ++ks)
            ldsm4(qa[mb][ks][0], qa[mb][ks][1], qa[mb][ks][2], qa[mb][ks][3],
                  addrA + ks * 32);
    }

    // per-thread FM smem row pointers (half2): rows wq+16mb+g (+8)
    const __half2* fmp[2][2];
    #pragma unroll
    for (int mb = 0; mb < 2; ++mb) {
        fmp[mb][0] = (const __half2*)(FMs + (wq + 16 * mb + g) * STRD) + tg;
        fmp[mb][1] = (const __half2*)(FMs + (wq + 16 * mb + g + 8) * STRD) + tg;
    }

    // ---------------- pass 1: row sums Z ----------------
    float z[2][2] = {{0.0f, 0.0f}, {0.0f, 0.0f}};
    for (int kt = 0; kt < Sc / TK; ++kt) {
        __syncthreads();
        #pragma unroll
        for (int i = tid; i < TK * 8; i += NTH) {      // K tile (fp16 memcpy)
            int r = i >> 3, c = (i & 7) * 8;
            *(uint4*)(Ks + r * STRD + c) =
                *(const uint4*)(Kh + (size_t)(kt * TK + r) * Dc + c);
        }
        #pragma unroll
        for (int i = tid; i < TQ * 8; i += NTH) {      // FM tile
            int r = i >> 3, c = (i & 7) * 8;
            *(uint4*)(FMs + r * STRD + c) =
                *(const uint4*)(FMg + (size_t)r * Sc + kt * TK + c);
        }
        __syncthreads();

        float sacc[2][8][4];
        #pragma unroll
        for (int mb = 0; mb < 2; ++mb)
            #pragma unroll
            for (int nt = 0; nt < 8; ++nt)
                sacc[mb][nt][0] = sacc[mb][nt][1] = sacc[mb][nt][2] = sacc[mb][nt][3] = 0.0f;

        #pragma unroll
        for (int ks = 0; ks < 4; ++ks) {
            unsigned bf[4][4];
            #pragma unroll
            for (int ntp = 0; ntp < 4; ++ntp)
                ldsm4(bf[ntp][0], bf[ntp][1], bf[ntp][2], bf[ntp][3],
                      addrB + (ntp * 16 * STRD + ks * 16) * 2);
            #pragma unroll
            for (int mb = 0; mb < 2; ++mb)
                #pragma unroll
                for (int ntp = 0; ntp < 4; ++ntp) {
                    mma_f16(sacc[mb][2 * ntp],     qa[mb][ks], &bf[ntp][0]);
                    mma_f16(sacc[mb][2 * ntp + 1], qa[mb][ks], &bf[ntp][2]);
                }
        }

        #pragma unroll
        for (int mb = 0; mb < 2; ++mb)
            #pragma unroll
            for (int nt = 0; nt < 8; ++nt) {
                float2 flo = __half22float2(fmp[mb][0][nt * 4]);
                float2 fhi = __half22float2(fmp[mb][1][nt * 4]);
                z[mb][0] += __expf(fmaf(sacc[mb][nt][0], SCALE, flo.x))
                          + __expf(fmaf(sacc[mb][nt][1], SCALE, flo.y));
                z[mb][1] += __expf(fmaf(sacc[mb][nt][2], SCALE, fhi.x))
                          + __expf(fmaf(sacc[mb][nt][3], SCALE, fhi.y));
            }
    }
    float iz[2][2];
    #pragma unroll
    for (int mb = 0; mb < 2; ++mb)
        #pragma unroll
        for (int half = 0; half < 2; ++half) {
            float zz = z[mb][half];
            zz += __shfl_xor_sync(0xffffffffu, zz, 1);
            zz += __shfl_xor_sync(0xffffffffu, zz, 2);
            iz[mb][half] = 1.0f / zz;
        }

    // ---------------- pass 2: emit P, accumulate O ----------------
    float oacc[2][8][4];
    #pragma unroll
    for (int mb = 0; mb < 2; ++mb)
        #pragma unroll
        for (int nt = 0; nt < 8; ++nt)
            oacc[mb][nt][0] = oacc[mb][nt][1] = oacc[mb][nt][2] = oacc[mb][nt][3] = 0.0f;

    float2* Pp[2][2];
    #pragma unroll
    for (int mb = 0; mb < 2; ++mb) {
        Pp[mb][0] = (float2*)(Pg + (size_t)(wq + 16 * mb + g) * Sc) + tg;
        Pp[mb][1] = (float2*)(Pg + (size_t)(wq + 16 * mb + g + 8) * Sc) + tg;
    }

    for (int kt = 0; kt < Sc / TK; ++kt) {
        __syncthreads();
        #pragma unroll
        for (int i = tid; i < TK * 8; i += NTH) {      // K tile
            int r = i >> 3, c = (i & 7) * 8;
            *(uint4*)(Ks + r * STRD + c) =
                *(const uint4*)(Kh + (size_t)(kt * TK + r) * Dc + c);
        }
        #pragma unroll
        for (int i = tid; i < TK * 8; i += NTH) {      // V tile
            int r = i >> 3, c = (i & 7) * 8;
            *(uint4*)(Vs + r * STRD + c) =
                *(const uint4*)(Vh + (size_t)(kt * TK + r) * Dc + c);
        }
        #pragma unroll
        for (int i = tid; i < TQ * 8; i += NTH) {      // FM tile
            int r = i >> 3, c = (i & 7) * 8;
            *(uint4*)(FMs + r * STRD + c) =
                *(const uint4*)(FMg + (size_t)r * Sc + kt * TK + c);
        }
        __syncthreads();

        float sacc[2][8][4];
        #pragma unroll
        for (int mb = 0; mb < 2; ++mb)
            #pragma unroll
            for (int nt = 0; nt < 8; ++nt)
                sacc[mb][nt][0] = sacc[mb][nt][1] = sacc[mb][nt][2] = sacc[mb][nt][3] = 0.0f;

        #pragma unroll
        for (int ks = 0; ks < 4; ++ks) {
            unsigned bf[4][4];
            #pragma unroll
            for (int ntp = 0; ntp < 4; ++ntp)
                ldsm4(bf[ntp][0], bf[ntp][1], bf[ntp][2], bf[ntp][3],
                      addrB + (ntp * 16 * STRD + ks * 16) * 2);
            #pragma unroll
            for (int mb = 0; mb < 2; ++mb)
                #pragma unroll
                for (int ntp = 0; ntp < 4; ++ntp) {
                    mma_f16(sacc[mb][2 * ntp],     qa[mb][ks], &bf[ntp][0]);
                    mma_f16(sacc[mb][2 * ntp + 1], qa[mb][ks], &bf[ntp][2]);
                }
        }

        // exp + normalize; emit P; pack fp16 A-fragments for PV
        unsigned phl[2][8], phh[2][8];
        #pragma unroll
        for (int mb = 0; mb < 2; ++mb) {
            #pragma unroll
            for (int nt = 0; nt < 8; ++nt) {
                float2 flo = __half22float2(fmp[mb][0][nt * 4]);
                float2 fhi = __half22float2(fmp[mb][1][nt * 4]);
                float p0 = __expf(fmaf(sacc[mb][nt][0], SCALE, flo.x)) * iz[mb][0];
                float p1 = __expf(fmaf(sacc[mb][nt][1], SCALE, flo.y)) * iz[mb][0];
                float p2 = __expf(fmaf(sacc[mb][nt][2], SCALE, fhi.x)) * iz[mb][1];
                float p3 = __expf(fmaf(sacc[mb][nt][3], SCALE, fhi.y)) * iz[mb][1];
                if (writep) {
                    __stwt(Pp[mb][0] + kt * 32 + nt * 4, make_float2(p0, p1));
                    __stwt(Pp[mb][1] + kt * 32 + nt * 4, make_float2(p2, p3));
                }
                __half2 hlo = __floats2half2_rn(p0, p1);
                __half2 hhi = __floats2half2_rn(p2, p3);
                phl[mb][nt] = *(unsigned*)&hlo;
                phh[mb][nt] = *(unsigned*)&hhi;
            }
        }

        // PV: V fragments ldsm'd once, shared across both m-blocks
        #pragma unroll
        for (int ks2 = 0; ks2 < 4; ++ks2) {
            #pragma unroll
            for (int ntp = 0; ntp < 4; ++ntp) {
                unsigned v0, v1, v2, v3;
                ldsm4t(v0, v1, v2, v3, addrV + (ks2 * 16 * STRD + ntp * 16) * 2);
                unsigned blo[2] = {v0, v1}, bhi[2] = {v2, v3};
                #pragma unroll
                for (int mb = 0; mb < 2; ++mb) {
                    unsigned a[4] = {phl[mb][2 * ks2], phh[mb][2 * ks2],
                                     phl[mb][2 * ks2 + 1], phh[mb][2 * ks2 + 1]};
                    mma_f16(oacc[mb][2 * ntp],     a, blo);
                    mma_f16(oacc[mb][2 * ntp + 1], a, bhi);
                }
            }
        }
    }

    // write O tile
    #pragma unroll
    for (int mb = 0; mb < 2; ++mb) {
        float* o0 = Og + (size_t)(wq + 16 * mb + g) * Dc;
        float* o1 = Og + (size_t)(wq + 16 * mb + g + 8) * Dc;
        #pragma unroll
        for (int nt = 0; nt < 8; ++nt) {
            int col = nt * 8 + 2 * tg;
            *(float2*)(o0 + col) = make_float2(oacc[mb][nt][0], oacc[mb][nt][1]);
            *(float2*)(o1 + col) = make_float2(oacc[mb][nt][2], oacc[mb][nt][3]);
        }
    }
}

extern "C" void kernel_launch(void* const* d_in, const int* in_sizes, int n_in,
                              void* d_out, int out_size) {
    const float* Q    = (const float*)d_in[0];
    const float* K    = (const float*)d_in[1];
    const float* V    = (const float*)d_in[2];
    const float* freq = (const float*)d_in[3];
    const int*   mask = (const int*)d_in[4];

    const size_t out_elems = (size_t)Bc * Hc * Sc * Dc;   // 3,145,728
    float* Out  = (float*)d_out;
    float* Pout = (float*)d_out + out_elems;              // p_attn follows out
    int writep  = (out_size > (int)out_elems) ? 1 : 0;

    {
        int total = Bc * Sc * Sc;
        prep_fm_kernel<<<total / (256 * 4), 256>>>(freq, mask);
    }
    {
        int total = Bc * Hc * Sc * Dc;
        prep_kv_kernel<<<total / (256 * 8), 256>>>(K, V);
    }
    {
        dim3 grid(Hc, Sc / TQ, Bc);
        attn_kernel<<<grid, NTH>>>(Q, Out, Pout, writep);
    }
}

// round 9
// speedup vs baseline: 1.9561x; 1.4331x over previous
#include <cuda_runtime.h>
#include <cuda_fp16.h>

#define Bc 2
#define Hc 12
#define Sc 2048
#define Dc 64
#define TQ 128
#define TK 64
#define NTH 128
#define STRD 72           // smem row stride in halves (64 + 8 pad, 144B)
#define SCALE 0.125f      // 1/sqrt(64)

// scratch: fp16 log(freq)/-60000, fp16 K, fp16 V, fp16 unnormalized exp fragments
__device__ __align__(16) __half g_fm[(size_t)Bc * Sc * Sc];
__device__ __align__(16) __half g_kh[(size_t)Bc * Hc * Sc * Dc];
__device__ __align__(16) __half g_vh[(size_t)Bc * Hc * Sc * Dc];
__device__ __align__(16) unsigned g_ps[(size_t)Bc * Hc * Sc * Sc / 2];  // 201 MB

__global__ void prep_fm_kernel(const float* __restrict__ freq,
                               const int*  __restrict__ mask) {
    size_t base = ((size_t)blockIdx.x * blockDim.x + threadIdx.x) * 4;
    float4 f = *(const float4*)(freq + base);
    int4   m = *(const int4*)(mask + base);
    __half2 lo = __floats2half2_rn(m.x ? __logf(f.x) : -60000.0f,
                                   m.y ? __logf(f.y) : -60000.0f);
    __half2 hi = __floats2half2_rn(m.z ? __logf(f.z) : -60000.0f,
                                   m.w ? __logf(f.w) : -60000.0f);
    uint2 u;
    u.x = *(unsigned*)&lo;
    u.y = *(unsigned*)&hi;
    *(uint2*)(g_fm + base) = u;
}

__global__ void prep_kv_kernel(const float* __restrict__ K,
                               const float* __restrict__ V) {
    size_t base = ((size_t)blockIdx.x * blockDim.x + threadIdx.x) * 8;
    float4 a = *(const float4*)(K + base);
    float4 b = *(const float4*)(K + base + 4);
    __half2 h0 = __floats2half2_rn(a.x, a.y), h1 = __floats2half2_rn(a.z, a.w);
    __half2 h2 = __floats2half2_rn(b.x, b.y), h3 = __floats2half2_rn(b.z, b.w);
    uint4 u;
    u.x = *(unsigned*)&h0; u.y = *(unsigned*)&h1;
    u.z = *(unsigned*)&h2; u.w = *(unsigned*)&h3;
    *(uint4*)(g_kh + base) = u;
    a = *(const float4*)(V + base);
    b = *(const float4*)(V + base + 4);
    h0 = __floats2half2_rn(a.x, a.y); h1 = __floats2half2_rn(a.z, a.w);
    h2 = __floats2half2_rn(b.x, b.y); h3 = __floats2half2_rn(b.z, b.w);
    u.x = *(unsigned*)&h0; u.y = *(unsigned*)&h1;
    u.z = *(unsigned*)&h2; u.w = *(unsigned*)&h3;
    *(uint4*)(g_vh + base) = u;
}

__device__ __forceinline__ void mma_f16(float* c, const unsigned* a, const unsigned* b) {
    asm volatile(
        "mma.sync.aligned.m16n8k16.row.col.f32.f16.f16.f32 "
        "{%0,%1,%2,%3}, {%4,%5,%6,%7}, {%8,%9}, {%0,%1,%2,%3};\n"
        : "+f"(c[0]), "+f"(c[1]), "+f"(c[2]), "+f"(c[3])
        : "r"(a[0]), "r"(a[1]), "r"(a[2]), "r"(a[3]), "r"(b[0]), "r"(b[1]));
}

__device__ __forceinline__ void ldsm4(unsigned& r0, unsigned& r1, unsigned& r2,
                                      unsigned& r3, unsigned addr) {
    asm volatile("ldmatrix.sync.aligned.m8n8.x4.shared.b16 {%0,%1,%2,%3}, [%4];"
                 : "=r"(r0), "=r"(r1), "=r"(r2), "=r"(r3) : "r"(addr));
}

__device__ __forceinline__ void ldsm4t(unsigned& r0, unsigned& r1, unsigned& r2,
                                       unsigned& r3, unsigned addr) {
    asm volatile("ldmatrix.sync.aligned.m8n8.x4.trans.shared.b16 {%0,%1,%2,%3}, [%4];"
                 : "=r"(r0), "=r"(r1), "=r"(r2), "=r"(r3) : "r"(addr));
}

__global__ void __launch_bounds__(NTH)
attn_kernel(const float* __restrict__ Q, float* __restrict__ Out,
            float* __restrict__ Pout, int writep) {
    // smem: [Ks 64 | FMs 128] x STRD ; pass2 overlays Vs on Ks; Q staging transient
    __shared__ __align__(16) __half smem_buf[(TK + TQ) * STRD];
    __half* Ks  = smem_buf;                       // 64  x STRD (pass1) / Vs (pass2)
    __half* FMs = smem_buf + TK * STRD;           // 128 x STRD (pass1)
    __half* Qst = smem_buf;                       // 128 x STRD transient

    const int tid = threadIdx.x;
    const int w = tid >> 5, lane = tid & 31;
    const int g = lane >> 2, tg = lane & 3;
    const int wq = w * 32;                        // warp's 32-row base
    const int h = blockIdx.x, qt = blockIdx.y, b = blockIdx.z;
    const int q0 = qt * TQ;

    const size_t bh = (size_t)b * Hc + h;
    const float*  Qg = Q + (bh * Sc + q0) * Dc;
    const __half* Kh = g_kh + bh * Sc * Dc;
    const __half* Vh = g_vh + bh * Sc * Dc;
    const __half* FMg = g_fm + (size_t)b * Sc * Sc + (size_t)q0 * Sc;
    float* Og = Out + (bh * Sc + q0) * Dc;
    float* Pg = Pout + (bh * Sc + q0) * Sc;

    // scratch fragment base for this (bh, qt, w): [kt][w][mb][i4][lane][uint4]
    uint4* scr = (uint4*)g_ps +
                 ((((bh * (Sc / TQ) + qt) * (Sc / TK)) * 4 + w) * 2) * 128 + lane;

    const unsigned smem_u = (unsigned)__cvta_generic_to_shared(smem_buf);
    const unsigned fms_u  = smem_u + TK * STRD * 2;
    // B (K): m0=(n0-7,klo) m1=(n0-7,khi) m2=(n8-15,klo) m3=(n8-15,khi)
    const int brow = ((lane >> 4) & 1) * 8 + (lane & 7);
    const int bcol = ((lane >> 3) & 1) * 8;
    const unsigned addrB = smem_u + ((brow * STRD + bcol) << 1);
    // V (trans) over the same smem region in pass 2
    const int vrow = ((lane >> 3) & 1) * 8 + (lane & 7);
    const int vcol = ((lane >> 4) & 1) * 8;
    const unsigned addrV = smem_u + ((vrow * STRD + vcol) << 1);
    // FM fragments (A/C layout) per m-block
    unsigned addrFM[2];
    #pragma unroll
    for (int mb = 0; mb < 2; ++mb)
        addrFM[mb] = fms_u +
            (((wq + 16 * mb + (lane & 15)) * STRD + (lane >> 4) * 8) << 1);

    // ---- stage Q tile fp32->fp16, load A-fragments into registers ----
    #pragma unroll
    for (int i = tid; i < TQ * 16; i += NTH) {
        int r = i >> 4, c = (i & 15) * 4;
        float4 v = *(const float4*)(Qg + (size_t)r * Dc + c);
        __half2 p0 = __floats2half2_rn(v.x, v.y), p1 = __floats2half2_rn(v.z, v.w);
        uint2 u; u.x = *(unsigned*)&p0; u.y = *(unsigned*)&p1;
        *(uint2*)(Qst + r * STRD + c) = u;
    }
    __syncthreads();
    unsigned qa[2][4][4];
    #pragma unroll
    for (int mb = 0; mb < 2; ++mb) {
        unsigned addrA = smem_u +
            (((wq + 16 * mb + (lane & 15)) * STRD + (lane >> 4) * 8) << 1);
        #pragma unroll
        for (int ks = 0; ks < 4; ++ks)
            ldsm4(qa[mb][ks][0], qa[mb][ks][1], qa[mb][ks][2], qa[mb][ks][3],
                  addrA + ks * 32);
    }

    // ---------------- pass 1: scores -> exp fragments + Z ----------------
    float z[2][2] = {{0.0f, 0.0f}, {0.0f, 0.0f}};
    for (int kt = 0; kt < Sc / TK; ++kt) {
        __syncthreads();
        #pragma unroll
        for (int i = tid; i < TK * 8; i += NTH) {      // K tile
            int r = i >> 3, c = (i & 7) * 8;
            *(uint4*)(Ks + r * STRD + c) =
                *(const uint4*)(Kh + (size_t)(kt * TK + r) * Dc + c);
        }
        #pragma unroll
        for (int i = tid; i < TQ * 8; i += NTH) {      // FM tile
            int r = i >> 3, c = (i & 7) * 8;
            *(uint4*)(FMs + r * STRD + c) =
                *(const uint4*)(FMg + (size_t)r * Sc + kt * TK + c);
        }
        __syncthreads();

        float sacc[2][8][4];
        #pragma unroll
        for (int mb = 0; mb < 2; ++mb)
            #pragma unroll
            for (int nt = 0; nt < 8; ++nt)
                sacc[mb][nt][0] = sacc[mb][nt][1] = sacc[mb][nt][2] = sacc[mb][nt][3] = 0.0f;

        #pragma unroll
        for (int ks = 0; ks < 4; ++ks) {
            unsigned bf[4][4];
            #pragma unroll
            for (int ntp = 0; ntp < 4; ++ntp)
                ldsm4(bf[ntp][0], bf[ntp][1], bf[ntp][2], bf[ntp][3],
                      addrB + (ntp * 16 * STRD + ks * 16) * 2);
            #pragma unroll
            for (int mb = 0; mb < 2; ++mb)
                #pragma unroll
                for (int ntp = 0; ntp < 4; ++ntp) {
                    mma_f16(sacc[mb][2 * ntp],     qa[mb][ks], &bf[ntp][0]);
                    mma_f16(sacc[mb][2 * ntp + 1], qa[mb][ks], &bf[ntp][2]);
                }
        }

        // exp via FM ldmatrix fragments; store unnormalized fp16 exp to scratch
        #pragma unroll
        for (int mb = 0; mb < 2; ++mb) {
            unsigned sl[8], sh[8];
            #pragma unroll
            for (int q4 = 0; q4 < 4; ++q4) {
                unsigned f0, f1, f2, f3;
                ldsm4(f0, f1, f2, f3, addrFM[mb] + q4 * 32);
                unsigned fr[2][2] = {{f0, f1}, {f2, f3}};
                #pragma unroll
                for (int j = 0; j < 2; ++j) {
                    int nt = 2 * q4 + j;
                    float2 flo = __half22float2(*(__half2*)&fr[j][0]);
                    float2 fhi = __half22float2(*(__half2*)&fr[j][1]);
                    float p0 = __expf(fmaf(sacc[mb][nt][0], SCALE, flo.x));
                    float p1 = __expf(fmaf(sacc[mb][nt][1], SCALE, flo.y));
                    float p2 = __expf(fmaf(sacc[mb][nt][2], SCALE, fhi.x));
                    float p3 = __expf(fmaf(sacc[mb][nt][3], SCALE, fhi.y));
                    z[mb][0] += p0 + p1;
                    z[mb][1] += p2 + p3;
                    __half2 hlo = __floats2half2_rn(p0, p1);
                    __half2 hhi = __floats2half2_rn(p2, p3);
                    sl[nt] = *(unsigned*)&hlo;
                    sh[nt] = *(unsigned*)&hhi;
                }
            }
            uint4* sp = scr + ((size_t)kt * 8 + mb) * 128;   // 8 = 4w*2mb blocks/kt
            sp[0]  = make_uint4(sl[0], sl[1], sl[2], sl[3]);
            sp[32] = make_uint4(sl[4], sl[5], sl[6], sl[7]);
            sp[64] = make_uint4(sh[0], sh[1], sh[2], sh[3]);
            sp[96] = make_uint4(sh[4], sh[5], sh[6], sh[7]);
        }
    }
    float iz[2][2];
    #pragma unroll
    for (int mb = 0; mb < 2; ++mb)
        #pragma unroll
        for (int hf = 0; hf < 2; ++hf) {
            float zz = z[mb][hf];
            zz += __shfl_xor_sync(0xffffffffu, zz, 1);
            zz += __shfl_xor_sync(0xffffffffu, zz, 2);
            iz[mb][hf] = 1.0f / zz;
        }

    // ---------------- pass 2: normalize P + PV (no QK recompute) ----------------
    float oacc[2][8][4];
    #pragma unroll
    for (int mb = 0; mb < 2; ++mb)
        #pragma unroll
        for (int nt = 0; nt < 8; ++nt)
            oacc[mb][nt][0] = oacc[mb][nt][1] = oacc[mb][nt][2] = oacc[mb][nt][3] = 0.0f;

    float2* Pp[2][2];
    #pragma unroll
    for (int mb = 0; mb < 2; ++mb) {
        Pp[mb][0] = (float2*)(Pg + (size_t)(wq + 16 * mb + g) * Sc) + tg;
        Pp[mb][1] = (float2*)(Pg + (size_t)(wq + 16 * mb + g + 8) * Sc) + tg;
    }

    for (int kt = 0; kt < Sc / TK; ++kt) {
        __syncthreads();
        #pragma unroll
        for (int i = tid; i < TK * 8; i += NTH) {      // V tile (overlays Ks)
            int r = i >> 3, c = (i & 7) * 8;
            *(uint4*)(Ks + r * STRD + c) =
                *(const uint4*)(Vh + (size_t)(kt * TK + r) * Dc + c);
        }
        __syncthreads();

        // read back exp fragments, emit normalized fp32 P
        unsigned sl[2][8], sh[2][8];
        #pragma unroll
        for (int mb = 0; mb < 2; ++mb) {
            uint4* sp = scr + ((size_t)kt * 8 + mb) * 128;
            uint4 a0 = sp[0], a1 = sp[32], a2 = sp[64], a3 = sp[96];
            sl[mb][0] = a0.x; sl[mb][1] = a0.y; sl[mb][2] = a0.z; sl[mb][3] = a0.w;
            sl[mb][4] = a1.x; sl[mb][5] = a1.y; sl[mb][6] = a1.z; sl[mb][7] = a1.w;
            sh[mb][0] = a2.x; sh[mb][1] = a2.y; sh[mb][2] = a2.z; sh[mb][3] = a2.w;
            sh[mb][4] = a3.x; sh[mb][5] = a3.y; sh[mb][6] = a3.z; sh[mb][7] = a3.w;
            if (writep) {
                #pragma unroll
                for (int nt = 0; nt < 8; ++nt) {
                    float2 plo = __half22float2(*(__half2*)&sl[mb][nt]);
                    float2 phi = __half22float2(*(__half2*)&sh[mb][nt]);
                    __stwt(Pp[mb][0] + kt * 32 + nt * 4,
                           make_float2(plo.x * iz[mb][0], plo.y * iz[mb][0]));
                    __stwt(Pp[mb][1] + kt * 32 + nt * 4,
                           make_float2(phi.x * iz[mb][1], phi.y * iz[mb][1]));
                }
            }
        }

        // PV with unnormalized fp16 fragments (scale applied at the end)
        #pragma unroll
        for (int ks2 = 0; ks2 < 4; ++ks2) {
            #pragma unroll
            for (int ntp = 0; ntp < 4; ++ntp) {
                unsigned v0, v1, v2, v3;
                ldsm4t(v0, v1, v2, v3, addrV + (ks2 * 16 * STRD + ntp * 16) * 2);
                unsigned blo[2] = {v0, v1}, bhi[2] = {v2, v3};
                #pragma unroll
                for (int mb = 0; mb < 2; ++mb) {
                    unsigned a[4] = {sl[mb][2 * ks2], sh[mb][2 * ks2],
                                     sl[mb][2 * ks2 + 1], sh[mb][2 * ks2 + 1]};
                    mma_f16(oacc[mb][2 * ntp],     a, blo);
                    mma_f16(oacc[mb][2 * ntp + 1], a, bhi);
                }
            }
        }
    }

    // scale by 1/Z and write O tile
    #pragma unroll
    for (int mb = 0; mb < 2; ++mb) {
        float* o0 = Og + (size_t)(wq + 16 * mb + g) * Dc;
        float* o1 = Og + (size_t)(wq + 16 * mb + g + 8) * Dc;
        #pragma unroll
        for (int nt = 0; nt < 8; ++nt) {
            int col = nt * 8 + 2 * tg;
            *(float2*)(o0 + col) = make_float2(oacc[mb][nt][0] * iz[mb][0],
                                               oacc[mb][nt][1] * iz[mb][0]);
            *(float2*)(o1 + col) = make_float2(oacc[mb][nt][2] * iz[mb][1],
                                               oacc[mb][nt][3] * iz[mb][1]);
        }
    }
}

extern "C" void kernel_launch(void* const* d_in, const int* in_sizes, int n_in,
                              void* d_out, int out_size) {
    const float* Q    = (const float*)d_in[0];
    const float* K    = (const float*)d_in[1];
    const float* V    = (const float*)d_in[2];
    const float* freq = (const float*)d_in[3];
    const int*   mask = (const int*)d_in[4];

    const size_t out_elems = (size_t)Bc * Hc * Sc * Dc;   // 3,145,728
    float* Out  = (float*)d_out;
    float* Pout = (float*)d_out + out_elems;              // p_attn follows out
    int writep  = (out_size > (int)out_elems) ? 1 : 0;

    {
        int total = Bc * Sc * Sc;
        prep_fm_kernel<<<total / (256 * 4), 256>>>(freq, mask);
    }
    {
        int total = Bc * Hc * Sc * Dc;
        prep_kv_kernel<<<total / (256 * 8), 256>>>(K, V);
    }
    {
        dim3 grid(Hc, Sc / TQ, Bc);
        attn_kernel<<<grid, NTH>>>(Q, Out, Pout, writep);
    }
}

// round 12
// speedup vs baseline: 2.0816x; 1.0642x over previous
#include <cuda_runtime.h>
#include <cuda_fp16.h>

#define Bc 2
#define Hc 12
#define Sc 2048
#define Dc 64
#define TQ 128
#define TK 64
#define NTH 128
#define STRD 72           // smem row stride in halves (64 + 8 pad, 144B)
#define SCALE 0.125f      // 1/sqrt(64)
#define NKT (Sc / TK)     // 32

// scratch: FM in fragment order, fp16 K/V, fp16 unnormalized exp fragments
// g_fmp layout (uint4): (((b*16+qt)*32+kt)*8 + w*2+mb)*128 + part*32 + lane
//   part0 = lo-row nt0-3, part1 = lo nt4-7, part2 = hi nt0-3, part3 = hi nt4-7
__device__ __align__(16) uint4 g_fmp[(size_t)Bc * 16 * 32 * 8 * 128];
__device__ __align__(16) __half g_kh[(size_t)Bc * Hc * Sc * Dc];
__device__ __align__(16) __half g_vh[(size_t)Bc * Hc * Sc * Dc];
__device__ __align__(16) unsigned g_ps[(size_t)Bc * Hc * Sc * Sc / 2];  // 201 MB

__global__ void prep_fm_kernel(const float* __restrict__ freq,
                               const int*  __restrict__ mask) {
    unsigned idx = blockIdx.x * blockDim.x + threadIdx.x;   // one uint4 out
    int lane = idx & 31, part = (idx >> 5) & 3, mbw = (idx >> 7) & 7;
    int kt = (idx >> 10) & 31, qt = (idx >> 15) & 15, b = idx >> 19;
    int w = mbw >> 1, mb = mbw & 1;
    int g = lane >> 2, tg = lane & 3;
    int q = qt * TQ + w * 32 + mb * 16 + g + ((part >> 1) << 3);
    const float* fr = freq + ((size_t)b * Sc + q) * Sc;
    const int*   mr = mask + ((size_t)b * Sc + q) * Sc;
    int kbase = kt * 64 + (part & 1) * 32 + tg * 2;
    unsigned out[4];
    #pragma unroll
    for (int j = 0; j < 4; ++j) {
        int k = kbase + j * 8;
        float2 f = *(const float2*)(fr + k);
        int2   m = *(const int2*)(mr + k);
        __half2 h = __floats2half2_rn(m.x ? __logf(f.x) : -60000.0f,
                                      m.y ? __logf(f.y) : -60000.0f);
        out[j] = *(unsigned*)&h;
    }
    g_fmp[idx] = make_uint4(out[0], out[1], out[2], out[3]);
}

__global__ void prep_kv_kernel(const float* __restrict__ K,
                               const float* __restrict__ V) {
    size_t base = ((size_t)blockIdx.x * blockDim.x + threadIdx.x) * 8;
    float4 a = *(const float4*)(K + base);
    float4 b = *(const float4*)(K + base + 4);
    __half2 h0 = __floats2half2_rn(a.x, a.y), h1 = __floats2half2_rn(a.z, a.w);
    __half2 h2 = __floats2half2_rn(b.x, b.y), h3 = __floats2half2_rn(b.z, b.w);
    uint4 u;
    u.x = *(unsigned*)&h0; u.y = *(unsigned*)&h1;
    u.z = *(unsigned*)&h2; u.w = *(unsigned*)&h3;
    *(uint4*)(g_kh + base) = u;
    a = *(const float4*)(V + base);
    b = *(const float4*)(V + base + 4);
    h0 = __floats2half2_rn(a.x, a.y); h1 = __floats2half2_rn(a.z, a.w);
    h2 = __floats2half2_rn(b.x, b.y); h3 = __floats2half2_rn(b.z, b.w);
    u.x = *(unsigned*)&h0; u.y = *(unsigned*)&h1;
    u.z = *(unsigned*)&h2; u.w = *(unsigned*)&h3;
    *(uint4*)(g_vh + base) = u;
}

__device__ __forceinline__ void mma_f16(float* c, const unsigned* a, const unsigned* b) {
    asm volatile(
        "mma.sync.aligned.m16n8k16.row.col.f32.f16.f16.f32 "
        "{%0,%1,%2,%3}, {%4,%5,%6,%7}, {%8,%9}, {%0,%1,%2,%3};\n"
        : "+f"(c[0]), "+f"(c[1]), "+f"(c[2]), "+f"(c[3])
        : "r"(a[0]), "r"(a[1]), "r"(a[2]), "r"(a[3]), "r"(b[0]), "r"(b[1]));
}

__device__ __forceinline__ void ldsm4(unsigned& r0, unsigned& r1, unsigned& r2,
                                      unsigned& r3, unsigned addr) {
    asm volatile("ldmatrix.sync.aligned.m8n8.x4.shared.b16 {%0,%1,%2,%3}, [%4];"
                 : "=r"(r0), "=r"(r1), "=r"(r2), "=r"(r3) : "r"(addr));
}

__device__ __forceinline__ void ldsm4t(unsigned& r0, unsigned& r1, unsigned& r2,
                                       unsigned& r3, unsigned addr) {
    asm volatile("ldmatrix.sync.aligned.m8n8.x4.trans.shared.b16 {%0,%1,%2,%3}, [%4];"
                 : "=r"(r0), "=r"(r1), "=r"(r2), "=r"(r3) : "r"(addr));
}

__global__ void __launch_bounds__(NTH)
attn_kernel(const float* __restrict__ Q, float* __restrict__ Out,
            float* __restrict__ Pout, int writep) {
    // 128 x STRD halves: Q staging uses all 128 rows; K/V tiles use rows 0..63
    __shared__ __align__(16) __half smem_buf[2 * TK * STRD];
    __half* Ks = smem_buf;                       // 64 x STRD (K pass1 / V pass2)

    const int tid = threadIdx.x;
    const int w = tid >> 5, lane = tid & 31;
    const int g = lane >> 2, tg = lane & 3;
    const int wq = w * 32;
    const int h = blockIdx.x, qt = blockIdx.y, b = blockIdx.z;
    const int q0 = qt * TQ;

    const size_t bh = (size_t)b * Hc + h;
    const float*  Qg = Q + (bh * Sc + q0) * Dc;
    const __half* Kh = g_kh + bh * Sc * Dc;
    const __half* Vh = g_vh + bh * Sc * Dc;
    float* Og = Out + (bh * Sc + q0) * Dc;
    float* Pg = Pout + (bh * Sc + q0) * Sc;

    // scratch exp fragments (proven R9 layout)
    uint4* scr = (uint4*)g_ps +
                 ((((bh * (Sc / TQ) + qt) * NKT) * 4 + w) * 2) * 128 + lane;
    // FM fragments (h-independent -> 12-head L2 reuse)
    const uint4* fmb = g_fmp +
                 ((((size_t)b * 16 + qt) * NKT) * 8 + w * 2) * 128 + lane;

    const unsigned smem_u = (unsigned)__cvta_generic_to_shared(smem_buf);
    // B (K): m0=(n0-7,klo) m1=(n0-7,khi) m2=(n8-15,klo) m3=(n8-15,khi)
    const int brow = ((lane >> 4) & 1) * 8 + (lane & 7);
    const int bcol = ((lane >> 3) & 1) * 8;
    const unsigned addrB = smem_u + ((brow * STRD + bcol) << 1);
    // V (trans)
    const int vrow = ((lane >> 3) & 1) * 8 + (lane & 7);
    const int vcol = ((lane >> 4) & 1) * 8;
    const unsigned addrV = smem_u + ((vrow * STRD + vcol) << 1);

    // ---- stage Q tile fp32->fp16 (uses all 128 rows), load A-fragments ----
    #pragma unroll
    for (int i = tid; i < TQ * 16; i += NTH) {
        int r = i >> 4, c = (i & 15) * 4;
        float4 v = *(const float4*)(Qg + (size_t)r * Dc + c);
        __half2 p0 = __floats2half2_rn(v.x, v.y), p1 = __floats2half2_rn(v.z, v.w);
        uint2 u; u.x = *(unsigned*)&p0; u.y = *(unsigned*)&p1;
        *(uint2*)(smem_buf + r * STRD + c) = u;
    }
    __syncthreads();
    unsigned qa[2][4][4];
    #pragma unroll
    for (int mb = 0; mb < 2; ++mb) {
        unsigned addrA = smem_u +
            (((wq + 16 * mb + (lane & 15)) * STRD + (lane >> 4) * 8) << 1);
        #pragma unroll
        for (int ks = 0; ks < 4; ++ks)
            ldsm4(qa[mb][ks][0], qa[mb][ks][1], qa[mb][ks][2], qa[mb][ks][3],
                  addrA + ks * 32);
    }

    // ---------------- pass 1: scores -> exp fragments + Z ----------------
    float z[2][2] = {{0.0f, 0.0f}, {0.0f, 0.0f}};
    for (int kt = 0; kt < NKT; ++kt) {
        // FM fragment loads issued early (independent of smem)
        uint4 fm[2][4];
        #pragma unroll
        for (int mb = 0; mb < 2; ++mb) {
            const uint4* fp = fmb + ((size_t)kt * 8 + mb) * 128;
            fm[mb][0] = fp[0];  fm[mb][1] = fp[32];
            fm[mb][2] = fp[64]; fm[mb][3] = fp[96];
        }

        __syncthreads();
        #pragma unroll
        for (int i = tid; i < TK * 8; i += NTH) {      // K tile (uint4 copy)
            int r = i >> 3, c = (i & 7) * 8;
            *(uint4*)(Ks + r * STRD + c) =
                *(const uint4*)(Kh + (size_t)(kt * TK + r) * Dc + c);
        }
        __syncthreads();

        float sacc[2][8][4];
        #pragma unroll
        for (int mb = 0; mb < 2; ++mb)
            #pragma unroll
            for (int nt = 0; nt < 8; ++nt)
                sacc[mb][nt][0] = sacc[mb][nt][1] = sacc[mb][nt][2] = sacc[mb][nt][3] = 0.0f;

        #pragma unroll
        for (int ks = 0; ks < 4; ++ks) {
            unsigned bf[4][4];
            #pragma unroll
            for (int ntp = 0; ntp < 4; ++ntp)
                ldsm4(bf[ntp][0], bf[ntp][1], bf[ntp][2], bf[ntp][3],
                      addrB + (ntp * 16 * STRD + ks * 16) * 2);
            #pragma unroll
            for (int mb = 0; mb < 2; ++mb)
                #pragma unroll
                for (int ntp = 0; ntp < 4; ++ntp) {
                    mma_f16(sacc[mb][2 * ntp],     qa[mb][ks], &bf[ntp][0]);
                    mma_f16(sacc[mb][2 * ntp + 1], qa[mb][ks], &bf[ntp][2]);
                }
        }

        // exp with FM registers; store unnormalized fp16 exp fragments
        #pragma unroll
        for (int mb = 0; mb < 2; ++mb) {
            unsigned sl[8], sh[8];
            #pragma unroll
            for (int nt = 0; nt < 8; ++nt) {
                unsigned flo_u = ((const unsigned*)&fm[mb][nt >> 2])[nt & 3];
                unsigned fhi_u = ((const unsigned*)&fm[mb][2 + (nt >> 2)])[nt & 3];
                float2 flo = __half22float2(*(__half2*)&flo_u);
                float2 fhi = __half22float2(*(__half2*)&fhi_u);
                float p0 = __expf(fmaf(sacc[mb][nt][0], SCALE, flo.x));
                float p1 = __expf(fmaf(sacc[mb][nt][1], SCALE, flo.y));
                float p2 = __expf(fmaf(sacc[mb][nt][2], SCALE, fhi.x));
                float p3 = __expf(fmaf(sacc[mb][nt][3], SCALE, fhi.y));
                z[mb][0] += p0 + p1;
                z[mb][1] += p2 + p3;
                __half2 hlo = __floats2half2_rn(p0, p1);
                __half2 hhi = __floats2half2_rn(p2, p3);
                sl[nt] = *(unsigned*)&hlo;
                sh[nt] = *(unsigned*)&hhi;
            }
            uint4* sp = scr + ((size_t)kt * 8 + mb) * 128;
            sp[0]  = make_uint4(sl[0], sl[1], sl[2], sl[3]);
            sp[32] = make_uint4(sl[4], sl[5], sl[6], sl[7]);
            sp[64] = make_uint4(sh[0], sh[1], sh[2], sh[3]);
            sp[96] = make_uint4(sh[4], sh[5], sh[6], sh[7]);
        }
    }
    float iz[2][2];
    #pragma unroll
    for (int mb = 0; mb < 2; ++mb)
        #pragma unroll
        for (int hf = 0; hf < 2; ++hf) {
            float zz = z[mb][hf];
            zz += __shfl_xor_sync(0xffffffffu, zz, 1);
            zz += __shfl_xor_sync(0xffffffffu, zz, 2);
            iz[mb][hf] = 1.0f / zz;
        }

    // ---------------- pass 2: normalize P + PV ----------------
    float oacc[2][8][4];
    #pragma unroll
    for (int mb = 0; mb < 2; ++mb)
        #pragma unroll
        for (int nt = 0; nt < 8; ++nt)
            oacc[mb][nt][0] = oacc[mb][nt][1] = oacc[mb][nt][2] = oacc[mb][nt][3] = 0.0f;

    float2* Pp[2][2];
    #pragma unroll
    for (int mb = 0; mb < 2; ++mb) {
        Pp[mb][0] = (float2*)(Pg + (size_t)(wq + 16 * mb + g) * Sc) + tg;
        Pp[mb][1] = (float2*)(Pg + (size_t)(wq + 16 * mb + g + 8) * Sc) + tg;
    }

    for (int kt = 0; kt < NKT; ++kt) {
        // scratch exp-fragment readback issued early (independent of smem)
        unsigned sl[2][8], sh[2][8];
        #pragma unroll
        for (int mb = 0; mb < 2; ++mb) {
            uint4* sp = scr + ((size_t)kt * 8 + mb) * 128;
            uint4 a0 = sp[0], a1 = sp[32], a2 = sp[64], a3 = sp[96];
            sl[mb][0] = a0.x; sl[mb][1] = a0.y; sl[mb][2] = a0.z; sl[mb][3] = a0.w;
            sl[mb][4] = a1.x; sl[mb][5] = a1.y; sl[mb][6] = a1.z; sl[mb][7] = a1.w;
            sh[mb][0] = a2.x; sh[mb][1] = a2.y; sh[mb][2] = a2.z; sh[mb][3] = a2.w;
            sh[mb][4] = a3.x; sh[mb][5] = a3.y; sh[mb][6] = a3.z; sh[mb][7] = a3.w;
        }

        __syncthreads();
        #pragma unroll
        for (int i = tid; i < TK * 8; i += NTH) {      // V tile (uint4 copy)
            int r = i >> 3, c = (i & 7) * 8;
            *(uint4*)(Ks + r * STRD + c) =
                *(const uint4*)(Vh + (size_t)(kt * TK + r) * Dc + c);
        }
        __syncthreads();

        // emit normalized fp32 P
        if (writep) {
            #pragma unroll
            for (int mb = 0; mb < 2; ++mb)
                #pragma unroll
                for (int nt = 0; nt < 8; ++nt) {
                    float2 plo = __half22float2(*(__half2*)&sl[mb][nt]);
                    float2 phi = __half22float2(*(__half2*)&sh[mb][nt]);
                    __stwt(Pp[mb][0] + kt * 32 + nt * 4,
                           make_float2(plo.x * iz[mb][0], plo.y * iz[mb][0]));
                    __stwt(Pp[mb][1] + kt * 32 + nt * 4,
                           make_float2(phi.x * iz[mb][1], phi.y * iz[mb][1]));
                }
        }

        // PV with unnormalized fp16 fragments (scale at the end)
        #pragma unroll
        for (int ks2 = 0; ks2 < 4; ++ks2) {
            #pragma unroll
            for (int ntp = 0; ntp < 4; ++ntp) {
                unsigned v0, v1, v2, v3;
                ldsm4t(v0, v1, v2, v3, addrV + (ks2 * 16 * STRD + ntp * 16) * 2);
                unsigned blo[2] = {v0, v1}, bhi[2] = {v2, v3};
                #pragma unroll
                for (int mb = 0; mb < 2; ++mb) {
                    unsigned a[4] = {sl[mb][2 * ks2], sh[mb][2 * ks2],
                                     sl[mb][2 * ks2 + 1], sh[mb][2 * ks2 + 1]};
                    mma_f16(oacc[mb][2 * ntp],     a, blo);
                    mma_f16(oacc[mb][2 * ntp + 1], a, bhi);
                }
            }
        }
    }

    // scale by 1/Z and write O tile
    #pragma unroll
    for (int mb = 0; mb < 2; ++mb) {
        float* o0 = Og + (size_t)(wq + 16 * mb + g) * Dc;
        float* o1 = Og + (size_t)(wq + 16 * mb + g + 8) * Dc;
        #pragma unroll
        for (int nt = 0; nt < 8; ++nt) {
            int col = nt * 8 + 2 * tg;
            *(float2*)(o0 + col) = make_float2(oacc[mb][nt][0] * iz[mb][0],
                                               oacc[mb][nt][1] * iz[mb][0]);
            *(float2*)(o1 + col) = make_float2(oacc[mb][nt][2] * iz[mb][1],
                                               oacc[mb][nt][3] * iz[mb][1]);
        }
    }
}

extern "C" void kernel_launch(void* const* d_in, const int* in_sizes, int n_in,
                              void* d_out, int out_size) {
    const float* Q    = (const float*)d_in[0];
    const float* K    = (const float*)d_in[1];
    const float* V    = (const float*)d_in[2];
    const float* freq = (const float*)d_in[3];
    const int*   mask = (const int*)d_in[4];

    const size_t out_elems = (size_t)Bc * Hc * Sc * Dc;   // 3,145,728
    float* Out  = (float*)d_out;
    float* Pout = (float*)d_out + out_elems;              // p_attn follows out
    int writep  = (out_size > (int)out_elems) ? 1 : 0;

    {
        int total = Bc * 16 * 32 * 8 * 128;               // one thread per uint4
        prep_fm_kernel<<<total / 256, 256>>>(freq, mask);
    }
    {
        int total = Bc * Hc * Sc * Dc;
        prep_kv_kernel<<<total / (256 * 8), 256>>>(K, V);
    }
    {
        dim3 grid(Hc, Sc / TQ, Bc);
        attn_kernel<<<grid, NTH>>>(Q, Out, Pout, writep);
    }
}